// round 16
// baseline (speedup 1.0000x reference)
#include <cuda_runtime.h>

#define BATCH  512
#define SEQ    256
#define HID    768
#define NCLS   2
#define NCHUNK 8
#define CHUNK  32   // SEQ / NCHUNK  (contiguous chunks: R10-proven layout)
#define ROWS_PER_CTA 4

// Encoded pooled maxima [BATCH*2][HID] as order-preserving uint32 (3 MB).
// Zero-initialized at module load; gemv resets to 0 after consuming, so 0 is
// the state at the start of every call. 0 is a valid identity for atomicMax
// because enc(any finite float) > 0, and eff >= 1 guarantees every slot gets
// at least one real contribution (chunk 0 always covers row 0).
__device__ unsigned int g_pooledEnc[BATCH * 2 * HID];

// Monotonic float<->uint mapping: enc(a) < enc(b)  <=>  a < b  (finite floats)
__device__ __forceinline__ unsigned int enc_f32(float f) {
    unsigned int u = __float_as_uint(f);
    return (u & 0x80000000u) ? ~u : (u | 0x80000000u);
}
__device__ __forceinline__ float dec_f32(unsigned int u) {
    unsigned int b = (u & 0x80000000u) ? (u ^ 0x80000000u) : ~u;
    return __uint_as_float(b);
}

// One CTA per (batch, half, s-chunk). 192 threads, each owns one float4.
__global__ __launch_bounds__(192) void pool_kernel(
    const float* __restrict__ x1, const float* __restrict__ x2,
    const int*   __restrict__ m1, const int*   __restrict__ m2)
{
    const int b    = blockIdx.x;
    const int half = blockIdx.y;
    const int cz   = blockIdx.z;
    const int t    = threadIdx.x;  // 0..191

    const int* __restrict__ m = half ? m2 : m1;

    // ---- effective length: index of first 0 in mask row; none (or idx 0) -> SEQ.
    __shared__ int s_eff;
    if (t < 32) {
        int first_zero = SEQ;
        #pragma unroll
        for (int chunk = 0; chunk < SEQ / 32; chunk++) {
            int v = m[b * SEQ + chunk * 32 + t];
            unsigned zeros = __ballot_sync(0xffffffffu, v == 0);
            if (zeros != 0u) {
                first_zero = chunk * 32 + (__ffs(zeros) - 1);
                break;
            }
        }
        #pragma unroll
        for (int off = 16; off > 0; off >>= 1)
            first_zero = min(first_zero, __shfl_down_sync(0xffffffffu, first_zero, off));
        if (t == 0)
            s_eff = (first_zero == 0 || first_zero == SEQ) ? SEQ : first_zero;
    }
    __syncthreads();
    const int eff = s_eff;

    // Allow the dependent gemv grid to launch early (PDL). Its griddepcontrol.wait
    // still blocks until this entire grid completes and its memory is visible.
    asm volatile("griddepcontrol.launch_dependents;");

    const int s_begin = cz * CHUNK;
    const int s_end   = min(eff, s_begin + CHUNK);
    if (s_begin >= s_end) return;          // beyond eff: identity (0) already there

    const float* __restrict__ x = half ? x2 : x1;
    const float4* __restrict__ xp =
        reinterpret_cast<const float4*>(x + (size_t)b * SEQ * HID) + t;
    const int STRIDE4 = HID / 4;  // 192 float4 per s-row

    const float NEG = __int_as_float(0xff800000);  // -inf
    float4 a0 = make_float4(NEG, NEG, NEG, NEG);
    float4 a1 = a0, a2 = a0, a3 = a0;

    const int n = s_end - s_begin;
    const int stop8 = s_begin + (n & ~7);
    int s = s_begin;
    for (; s < stop8; s += 8) {
        float4 v0 = __ldcs(xp + (size_t)(s + 0) * STRIDE4);
        float4 v1 = __ldcs(xp + (size_t)(s + 1) * STRIDE4);
        float4 v2 = __ldcs(xp + (size_t)(s + 2) * STRIDE4);
        float4 v3 = __ldcs(xp + (size_t)(s + 3) * STRIDE4);
        float4 v4 = __ldcs(xp + (size_t)(s + 4) * STRIDE4);
        float4 v5 = __ldcs(xp + (size_t)(s + 5) * STRIDE4);
        float4 v6 = __ldcs(xp + (size_t)(s + 6) * STRIDE4);
        float4 v7 = __ldcs(xp + (size_t)(s + 7) * STRIDE4);
        a0.x = fmaxf(a0.x, fmaxf(v0.x, v4.x)); a0.y = fmaxf(a0.y, fmaxf(v0.y, v4.y));
        a0.z = fmaxf(a0.z, fmaxf(v0.z, v4.z)); a0.w = fmaxf(a0.w, fmaxf(v0.w, v4.w));
        a1.x = fmaxf(a1.x, fmaxf(v1.x, v5.x)); a1.y = fmaxf(a1.y, fmaxf(v1.y, v5.y));
        a1.z = fmaxf(a1.z, fmaxf(v1.z, v5.z)); a1.w = fmaxf(a1.w, fmaxf(v1.w, v5.w));
        a2.x = fmaxf(a2.x, fmaxf(v2.x, v6.x)); a2.y = fmaxf(a2.y, fmaxf(v2.y, v6.y));
        a2.z = fmaxf(a2.z, fmaxf(v2.z, v6.z)); a2.w = fmaxf(a2.w, fmaxf(v2.w, v6.w));
        a3.x = fmaxf(a3.x, fmaxf(v3.x, v7.x)); a3.y = fmaxf(a3.y, fmaxf(v3.y, v7.y));
        a3.z = fmaxf(a3.z, fmaxf(v3.z, v7.z)); a3.w = fmaxf(a3.w, fmaxf(v3.w, v7.w));
    }
    for (; s < s_end; s++) {
        float4 v0 = __ldcs(xp + (size_t)s * STRIDE4);
        a0.x = fmaxf(a0.x, v0.x); a0.y = fmaxf(a0.y, v0.y);
        a0.z = fmaxf(a0.z, v0.z); a0.w = fmaxf(a0.w, v0.w);
    }
    a0.x = fmaxf(fmaxf(a0.x, a1.x), fmaxf(a2.x, a3.x));
    a0.y = fmaxf(fmaxf(a0.y, a1.y), fmaxf(a2.y, a3.y));
    a0.z = fmaxf(fmaxf(a0.z, a1.z), fmaxf(a2.z, a3.z));
    a0.w = fmaxf(fmaxf(a0.w, a1.w), fmaxf(a2.w, a3.w));

    unsigned int* __restrict__ dst =
        g_pooledEnc + (size_t)(b * 2 + half) * HID + t * 4;
    atomicMax(dst + 0, enc_f32(a0.x));
    atomicMax(dst + 1, enc_f32(a0.y));
    atomicMax(dst + 2, enc_f32(a0.z));
    atomicMax(dst + 3, enc_f32(a0.w));
}

// One CTA (384 threads) per FOUR batch rows. PDL-launched: preloads W/bias
// (once, reused for all rows), griddepcontrol.wait, then 4 independent uint4
// pooled loads (MLP 4), FMA, four parallel reductions. Rows reset inline.
__global__ __launch_bounds__(384) void gemv_kernel(
    const float* __restrict__ W, const float* __restrict__ bias,
    float* __restrict__ out)
{
    const int bbase = blockIdx.x * ROWS_PER_CTA;
    const int t     = threadIdx.x;        // 0..383  (384 * 4 = 1536 = 2*HID)
    const int ROW4  = (2 * HID) / 4;      // uint4s per row

    uint4* __restrict__ p0 =
        reinterpret_cast<uint4*>(g_pooledEnc + (size_t)bbase * (2 * HID)) + t;
    const float4* __restrict__ W0 = reinterpret_cast<const float4*>(W) + t;
    const float4* __restrict__ W1 = W0 + ROW4;

    // Independent of the pool grid: fetch while pool is still streaming.
    float4 w0 = *W0;
    float4 w1 = *W1;
    float  c0 = bias[0];
    float  c1 = bias[1];

    // Wait for the pool grid to complete (and its atomics to be visible).
    asm volatile("griddepcontrol.wait;" ::: "memory");

    uint4 u[ROWS_PER_CTA];
    #pragma unroll
    for (int r = 0; r < ROWS_PER_CTA; r++) u[r] = p0[r * ROW4];
    #pragma unroll
    for (int r = 0; r < ROWS_PER_CTA; r++)
        p0[r * ROW4] = make_uint4(0u, 0u, 0u, 0u);   // reset for next replay

    float acc0[ROWS_PER_CTA], acc1[ROWS_PER_CTA];
    #pragma unroll
    for (int r = 0; r < ROWS_PER_CTA; r++) {
        float vx = dec_f32(u[r].x), vy = dec_f32(u[r].y);
        float vz = dec_f32(u[r].z), vw = dec_f32(u[r].w);
        acc0[r] = vx * w0.x + vy * w0.y + vz * w0.z + vw * w0.w;
        acc1[r] = vx * w1.x + vy * w1.y + vz * w1.z + vw * w1.w;
    }

    #pragma unroll
    for (int off = 16; off > 0; off >>= 1) {
        #pragma unroll
        for (int r = 0; r < ROWS_PER_CTA; r++) {
            acc0[r] += __shfl_down_sync(0xffffffffu, acc0[r], off);
            acc1[r] += __shfl_down_sync(0xffffffffu, acc1[r], off);
        }
    }
    __shared__ float s0[ROWS_PER_CTA][12], s1[ROWS_PER_CTA][12];
    if ((t & 31) == 0) {
        #pragma unroll
        for (int r = 0; r < ROWS_PER_CTA; r++) {
            s0[r][t >> 5] = acc0[r];
            s1[r][t >> 5] = acc1[r];
        }
    }
    __syncthreads();
    // Warp 0: lanes 0..11 hold partials for each row; reduce all 4 rows.
    if (t < 32) {
        #pragma unroll
        for (int r = 0; r < ROWS_PER_CTA; r++) {
            float r0 = (t < 12) ? s0[r][t] : 0.f;
            float r1 = (t < 12) ? s1[r][t] : 0.f;
            #pragma unroll
            for (int off = 8; off > 0; off >>= 1) {
                r0 += __shfl_down_sync(0xffffffffu, r0, off);
                r1 += __shfl_down_sync(0xffffffffu, r1, off);
            }
            if (t == 0) {
                out[(bbase + r) * NCLS + 0] = r0 + c0;
                out[(bbase + r) * NCLS + 1] = r1 + c1;
            }
        }
    }
}

extern "C" void kernel_launch(void* const* d_in, const int* in_sizes, int n_in,
                              void* d_out, int out_size)
{
    const float* x1 = (const float*)d_in[0];
    const float* x2 = (const float*)d_in[1];
    const int*   m1 = (const int*)  d_in[2];
    const int*   m2 = (const int*)  d_in[3];
    const float* W  = (const float*)d_in[4];
    const float* bs = (const float*)d_in[5];
    float* out = (float*)d_out;

    dim3 grid(BATCH, 2, NCHUNK);
    pool_kernel<<<grid, 192>>>(x1, x2, m1, m2);

    // Dependent launch with programmatic stream serialization (PDL).
    cudaLaunchConfig_t cfg = {};
    cfg.gridDim  = dim3(BATCH / ROWS_PER_CTA);
    cfg.blockDim = dim3(384);
    cfg.dynamicSmemBytes = 0;
    cfg.stream = 0;  // same (default) stream as pool_kernel
    cudaLaunchAttribute attr[1];
    attr[0].id = cudaLaunchAttributeProgrammaticStreamSerialization;
    attr[0].val.programmaticStreamSerializationAllowed = 1;
    cfg.attrs = attr;
    cfg.numAttrs = 1;
    cudaLaunchKernelEx(&cfg, gemv_kernel, W, bs, (float*)d_out);
}

// round 17
// speedup vs baseline: 1.0570x; 1.0570x over previous
#include <cuda_runtime.h>

#define BATCH  512
#define SEQ    256
#define HID    768
#define NCLS   2
#define NCHUNK 8
#define CHUNK  32   // SEQ / NCHUNK  (contiguous chunks; == warp size for 1-shot mask ballot)

// Encoded pooled maxima [BATCH*2][HID] as order-preserving uint32 (3 MB).
// Zero-initialized at module load; gemv resets to 0 after consuming, so 0 is
// the state at the start of every call. 0 is a valid identity for atomicMax
// because enc(any finite float) > 0, and eff >= 1 guarantees every slot gets
// at least one real contribution (chunk 0 always covers row 0).
__device__ unsigned int g_pooledEnc[BATCH * 2 * HID];

// Monotonic float<->uint mapping: enc(a) < enc(b)  <=>  a < b  (finite floats)
__device__ __forceinline__ unsigned int enc_f32(float f) {
    unsigned int u = __float_as_uint(f);
    return (u & 0x80000000u) ? ~u : (u | 0x80000000u);
}
__device__ __forceinline__ float dec_f32(unsigned int u) {
    unsigned int b = (u & 0x80000000u) ? (u ^ 0x80000000u) : ~u;
    return __uint_as_float(b);
}

// One CTA per (batch, half, s-chunk). 192 threads, each owns one float4.
// Masks are prefix masks (arange < length, length >= 1), so each chunk CTA can
// derive its own row count from JUST its 32 mask values: one load + one ballot.
__global__ __launch_bounds__(192) void pool_kernel(
    const float* __restrict__ x1, const float* __restrict__ x2,
    const int*   __restrict__ m1, const int*   __restrict__ m2)
{
    const int b    = blockIdx.x;
    const int half = blockIdx.y;
    const int cz   = blockIdx.z;
    const int t    = threadIdx.x;  // 0..191

    // Allow the dependent gemv grid to dispatch early (PDL); no dependencies.
    asm volatile("griddepcontrol.launch_dependents;");

    const int* __restrict__ m = half ? m2 : m1;
    const int s_begin = cz * CHUNK;

    // ---- chunk-local valid-row count (prefix-mask property) ----
    __shared__ int s_cnt;
    if (t < 32) {
        int v = m[b * SEQ + s_begin + t];          // one 32-lane load
        unsigned zeros = __ballot_sync(0xffffffffu, v == 0);
        if (t == 0)
            s_cnt = zeros ? (__ffs(zeros) - 1) : CHUNK;  // rows valid in this chunk
    }
    __syncthreads();
    const int cnt = s_cnt;
    if (cnt <= 0) return;                 // eff <= s_begin: identity already there

    const float* __restrict__ x = half ? x2 : x1;
    const float4* __restrict__ xp =
        reinterpret_cast<const float4*>(x + (size_t)b * SEQ * HID) + t;
    const int STRIDE4 = HID / 4;  // 192 float4 per s-row

    const float NEG = __int_as_float(0xff800000);  // -inf
    float4 a0 = make_float4(NEG, NEG, NEG, NEG);
    float4 a1 = a0, a2 = a0, a3 = a0;

    const int s_end = s_begin + cnt;
    const int stop8 = s_begin + (cnt & ~7);
    int s = s_begin;
    for (; s < stop8; s += 8) {
        float4 v0 = __ldcs(xp + (size_t)(s + 0) * STRIDE4);
        float4 v1 = __ldcs(xp + (size_t)(s + 1) * STRIDE4);
        float4 v2 = __ldcs(xp + (size_t)(s + 2) * STRIDE4);
        float4 v3 = __ldcs(xp + (size_t)(s + 3) * STRIDE4);
        float4 v4 = __ldcs(xp + (size_t)(s + 4) * STRIDE4);
        float4 v5 = __ldcs(xp + (size_t)(s + 5) * STRIDE4);
        float4 v6 = __ldcs(xp + (size_t)(s + 6) * STRIDE4);
        float4 v7 = __ldcs(xp + (size_t)(s + 7) * STRIDE4);
        a0.x = fmaxf(a0.x, fmaxf(v0.x, v4.x)); a0.y = fmaxf(a0.y, fmaxf(v0.y, v4.y));
        a0.z = fmaxf(a0.z, fmaxf(v0.z, v4.z)); a0.w = fmaxf(a0.w, fmaxf(v0.w, v4.w));
        a1.x = fmaxf(a1.x, fmaxf(v1.x, v5.x)); a1.y = fmaxf(a1.y, fmaxf(v1.y, v5.y));
        a1.z = fmaxf(a1.z, fmaxf(v1.z, v5.z)); a1.w = fmaxf(a1.w, fmaxf(v1.w, v5.w));
        a2.x = fmaxf(a2.x, fmaxf(v2.x, v6.x)); a2.y = fmaxf(a2.y, fmaxf(v2.y, v6.y));
        a2.z = fmaxf(a2.z, fmaxf(v2.z, v6.z)); a2.w = fmaxf(a2.w, fmaxf(v2.w, v6.w));
        a3.x = fmaxf(a3.x, fmaxf(v3.x, v7.x)); a3.y = fmaxf(a3.y, fmaxf(v3.y, v7.y));
        a3.z = fmaxf(a3.z, fmaxf(v3.z, v7.z)); a3.w = fmaxf(a3.w, fmaxf(v3.w, v7.w));
    }
    for (; s < s_end; s++) {
        float4 v0 = __ldcs(xp + (size_t)s * STRIDE4);
        a0.x = fmaxf(a0.x, v0.x); a0.y = fmaxf(a0.y, v0.y);
        a0.z = fmaxf(a0.z, v0.z); a0.w = fmaxf(a0.w, v0.w);
    }
    a0.x = fmaxf(fmaxf(a0.x, a1.x), fmaxf(a2.x, a3.x));
    a0.y = fmaxf(fmaxf(a0.y, a1.y), fmaxf(a2.y, a3.y));
    a0.z = fmaxf(fmaxf(a0.z, a1.z), fmaxf(a2.z, a3.z));
    a0.w = fmaxf(fmaxf(a0.w, a1.w), fmaxf(a2.w, a3.w));

    unsigned int* __restrict__ dst =
        g_pooledEnc + (size_t)(b * 2 + half) * HID + t * 4;
    atomicMax(dst + 0, enc_f32(a0.x));
    atomicMax(dst + 1, enc_f32(a0.y));
    atomicMax(dst + 2, enc_f32(a0.z));
    atomicMax(dst + 3, enc_f32(a0.w));
}

// One CTA (384 threads) per TWO batch rows (R15 measured-best). PDL-launched:
// preloads W/bias during the pool, griddepcontrol.wait, 2 independent uint4
// pooled loads, FMA, two parallel reductions. Rows reset inline.
__global__ __launch_bounds__(384) void gemv_kernel(
    const float* __restrict__ W, const float* __restrict__ bias,
    float* __restrict__ out)
{
    const int b0i = blockIdx.x * 2;       // rows b0i, b0i+1
    const int t   = threadIdx.x;          // 0..383  (384 * 4 = 1536 = 2*HID)

    uint4* __restrict__ pA =
        reinterpret_cast<uint4*>(g_pooledEnc + (size_t)b0i * (2 * HID)) + t;
    uint4* __restrict__ pB = pA + (2 * HID) / 4;   // next row
    const float4* __restrict__ W0 = reinterpret_cast<const float4*>(W) + t;
    const float4* __restrict__ W1 = W0 + (2 * HID) / 4;

    // Independent of the pool grid: fetch while pool is still streaming.
    float4 w0 = *W0;
    float4 w1 = *W1;
    float  c0 = bias[0];
    float  c1 = bias[1];

    // Wait for the pool grid to complete (and its atomics to be visible).
    asm volatile("griddepcontrol.wait;" ::: "memory");

    uint4 uA = *pA;
    uint4 uB = *pB;
    *pA = make_uint4(0u, 0u, 0u, 0u);   // reset for next replay
    *pB = make_uint4(0u, 0u, 0u, 0u);

    float ax = dec_f32(uA.x), ay = dec_f32(uA.y);
    float az = dec_f32(uA.z), aw = dec_f32(uA.w);
    float bx = dec_f32(uB.x), by = dec_f32(uB.y);
    float bz = dec_f32(uB.z), bw = dec_f32(uB.w);

    float a0 = ax * w0.x + ay * w0.y + az * w0.z + aw * w0.w;
    float a1 = ax * w1.x + ay * w1.y + az * w1.z + aw * w1.w;
    float b0 = bx * w0.x + by * w0.y + bz * w0.z + bw * w0.w;
    float b1 = bx * w1.x + by * w1.y + bz * w1.z + bw * w1.w;

    #pragma unroll
    for (int off = 16; off > 0; off >>= 1) {
        a0 += __shfl_down_sync(0xffffffffu, a0, off);
        a1 += __shfl_down_sync(0xffffffffu, a1, off);
        b0 += __shfl_down_sync(0xffffffffu, b0, off);
        b1 += __shfl_down_sync(0xffffffffu, b1, off);
    }
    __shared__ float sA0[12], sA1[12], sB0[12], sB1[12];
    if ((t & 31) == 0) {
        sA0[t >> 5] = a0; sA1[t >> 5] = a1;
        sB0[t >> 5] = b0; sB1[t >> 5] = b1;
    }
    __syncthreads();
    if (t < 32) {
        float rA0 = (t < 12) ? sA0[t] : 0.f;
        float rA1 = (t < 12) ? sA1[t] : 0.f;
        float rB0 = (t < 12) ? sB0[t] : 0.f;
        float rB1 = (t < 12) ? sB1[t] : 0.f;
        #pragma unroll
        for (int off = 8; off > 0; off >>= 1) {
            rA0 += __shfl_down_sync(0xffffffffu, rA0, off);
            rA1 += __shfl_down_sync(0xffffffffu, rA1, off);
            rB0 += __shfl_down_sync(0xffffffffu, rB0, off);
            rB1 += __shfl_down_sync(0xffffffffu, rB1, off);
        }
        if (t == 0) {
            out[b0i * NCLS + 0] = rA0 + c0;
            out[b0i * NCLS + 1] = rA1 + c1;
            out[(b0i + 1) * NCLS + 0] = rB0 + c0;
            out[(b0i + 1) * NCLS + 1] = rB1 + c1;
        }
    }
}

extern "C" void kernel_launch(void* const* d_in, const int* in_sizes, int n_in,
                              void* d_out, int out_size)
{
    const float* x1 = (const float*)d_in[0];
    const float* x2 = (const float*)d_in[1];
    const int*   m1 = (const int*)  d_in[2];
    const int*   m2 = (const int*)  d_in[3];
    const float* W  = (const float*)d_in[4];
    const float* bs = (const float*)d_in[5];
    float* out = (float*)d_out;

    dim3 grid(BATCH, 2, NCHUNK);
    pool_kernel<<<grid, 192>>>(x1, x2, m1, m2);

    // Dependent launch with programmatic stream serialization (PDL).
    cudaLaunchConfig_t cfg = {};
    cfg.gridDim  = dim3(BATCH / 2);
    cfg.blockDim = dim3(384);
    cfg.dynamicSmemBytes = 0;
    cfg.stream = 0;  // same (default) stream as pool_kernel
    cudaLaunchAttribute attr[1];
    attr[0].id = cudaLaunchAttributeProgrammaticStreamSerialization;
    attr[0].val.programmaticStreamSerializationAllowed = 1;
    cfg.attrs = attr;
    cfg.numAttrs = 1;
    cudaLaunchKernelEx(&cfg, gemv_kernel, W, bs, (float*)d_out);
}